// round 8
// baseline (speedup 1.0000x reference)
#include <cuda_runtime.h>

#define FULLMASK 0xffffffffu
#define MAX_PATCHES 32768

// Scratch: per-patch raw channel sums (mean*64), 32768 x 32 floats = 4MB.
__device__ float g_emb[MAX_PATCHES * 32];

// ============================================================================
// K1: pure streaming reduction (identical to R5's proven 42.4us kernel).
// One warp per patch; 16 x LDG.128 grouped (4-lane 64B chunks); epilogue is
// just 2 shfls + 1 predicated STG per pass -> warps return to loading fast.
// ============================================================================
__global__ void __launch_bounds__(256) reduce_kernel(
    const float* __restrict__ patch, int n_patches)
{
    const int wid  = threadIdx.x >> 5;
    const int lane = threadIdx.x & 31;
    const int n = blockIdx.x * 8 + wid;
    if (n >= n_patches) return;

    const float4* p4 = reinterpret_cast<const float4*>(patch) + (size_t)n * 512;

    float4 v[16];
#pragma unroll
    for (int t = 0; t < 16; t++) {
        const int p = t >> 2, q = t & 3;
        const int idx = p * 128 + (lane >> 2) * 16 + (lane & 3) + 4 * q;
        v[t] = p4[idx];
    }

#pragma unroll
    for (int p = 0; p < 4; p++) {
        float a = 0.0f;
#pragma unroll
        for (int q = 0; q < 4; q++) {
            const float4 x = v[p * 4 + q];
            a += (x.x + x.y) + (x.z + x.w);
        }
        a += __shfl_xor_sync(FULLMASK, a, 1);
        a += __shfl_xor_sync(FULLMASK, a, 2);
        if ((lane & 3) == 0)
            g_emb[n * 32 + p * 8 + (lane >> 2)] = a;   // raw channel sum
    }
}

// ============================================================================
// K2: THREAD-per-patch router math. No cross-lane ops, no serial shuffle
// chains — each thread is fully independent after keys are staged. 32768
// threads total; per-thread ~512 FMA + 5-element selection + transcendentals.
// ============================================================================
__global__ void __launch_bounds__(256) finalize_kernel(
    const float* __restrict__ keys,
    const float* __restrict__ p_temp,
    const float* __restrict__ p_beta,
    const float* __restrict__ p_thr,
    float* __restrict__ out,
    int n_patches)
{
    __shared__ float s_keys[16][32];   // all threads read same addr -> broadcast

    const int tid = threadIdx.x;
    for (int i = tid; i < 16 * 32; i += 256)
        s_keys[i >> 5][i & 31] = keys[i];
    __syncthreads();

    const int n = blockIdx.x * 256 + tid;
    if (n >= n_patches) return;

    const float logit_temp = __ldg(p_temp);
    const float mask_beta  = __ldg(p_beta);
    const float thr_base   = __ldg(p_thr);

    // ---- Load this patch's raw channel sums (8 x LDG.128) ----
    float emb[32];
    const float4* g4 = reinterpret_cast<const float4*>(&g_emb[n * 32]);
#pragma unroll
    for (int i = 0; i < 8; i++) {
        const float4 x = g4[i];
        emb[i * 4 + 0] = x.x; emb[i * 4 + 1] = x.y;
        emb[i * 4 + 2] = x.z; emb[i * 4 + 3] = x.w;
    }

    // ---- L2 norm ----
    float sq = 0.0f;
#pragma unroll
    for (int c = 0; c < 32; c++) sq = fmaf(emb[c], emb[c], sq);
    const float denom = fmaxf(sqrtf(sq), 64.0f * 1e-12f);

    // ---- Logits + softmax over 16 experts ----
    float w[16];
    float m = -1e30f;
#pragma unroll
    for (int e = 0; e < 16; e++) {
        float dot = 0.0f;
#pragma unroll
        for (int c = 0; c < 32; c++)
            dot = fmaf(emb[c], s_keys[e][c], dot);
        w[e] = (dot / denom) / logit_temp + 1e-8f;
        m = fmaxf(m, w[e]);
    }
    float S = 0.0f;
#pragma unroll
    for (int e = 0; e < 16; e++) { w[e] = __expf(w[e] - m); S += w[e]; }
    const float invS = 1.0f / S;
#pragma unroll
    for (int e = 0; e < 16; e++) w[e] *= invS;

    // ---- Top-5 values via selection (values only; ties irrelevant) ----
    float t[16];
#pragma unroll
    for (int e = 0; e < 16; e++) t[e] = w[e];
    float top[5];
#pragma unroll
    for (int k = 0; k < 5; k++) {
        float best = t[0]; int bi = 0;
#pragma unroll
        for (int e = 1; e < 16; e++)
            if (t[e] > best) { best = t[e]; bi = e; }
        top[k] = best;
        t[bi] = -1.0f;
    }
    const float s0   = top[0];
    const float rest = (top[1] + top[2] + top[3] + top[4]) * 0.25f;
    const float kth  = top[3];                         // 4th largest

    // ---- Moments & entropy ----
    float sum = 0.0f, ent = 0.0f;
#pragma unroll
    for (int e = 0; e < 16; e++) {
        sum += w[e];
        ent -= w[e] * __logf(w[e] + 1e-18f);
    }
    const float meanw = sum * (1.0f / 16.0f);
    float var = 0.0f;
#pragma unroll
    for (int e = 0; e < 16; e++) {
        const float d = w[e] - meanw;
        var = fmaf(d, d, var);
    }
    const float stdw = sqrtf(var * (1.0f / 15.0f));    // ddof=1

    // ---- Adaptive threshold ----
    const float maxc = 1.0f - s0;
    const float entc = 1.0f - ent * (1.0f / 2.7725887222397811f);   // 1/log(16)
    float gap = (s0 - rest) / (s0 + 1e-8f);
    gap = fminf(fmaxf(gap, 0.0f), 1.0f);
    const float af = 0.4f * maxc + 0.3f * entc + 0.3f * gap;
    float adaptive = thr_base * (0.5f + af);
    const float min_thr = fmaxf(0.05f, meanw - 0.5f * stdw);
    const float max_thr = fminf(0.7f, s0 - 0.1f * stdw);
    adaptive = fminf(fmaxf(adaptive, min_thr), max_thr);
    adaptive = fminf(adaptive, kth * 0.9f);

    // ---- Soft mask + renormalize ----
    float wf[16];
    float swf = 0.0f;
#pragma unroll
    for (int e = 0; e < 16; e++) {
        const float x  = (mask_beta + 1e-8f) * (w[e] - adaptive);
        const float sm = 1.0f / (1.0f + __expf(-x));
        wf[e] = w[e] * sm;
        swf += wf[e];
    }
    const float inv = 1.0f / fmaxf(swf, 1e-8f);

    // ---- Write 64B contiguous per thread (4 x ST.128) ----
    float4* o4 = reinterpret_cast<float4*>(out + (size_t)n * 16);
#pragma unroll
    for (int i = 0; i < 4; i++) {
        float4 r;
        r.x = wf[i * 4 + 0] * inv; r.y = wf[i * 4 + 1] * inv;
        r.z = wf[i * 4 + 2] * inv; r.w = wf[i * 4 + 3] * inv;
        o4[i] = r;
    }
}

extern "C" void kernel_launch(void* const* d_in, const int* in_sizes, int n_in,
                              void* d_out, int out_size) {
    const float* patch = (const float*)d_in[0];
    const float* keys  = (const float*)d_in[1];
    const float* temp  = (const float*)d_in[2];
    const float* beta  = (const float*)d_in[3];
    const float* thr   = (const float*)d_in[4];
    float* out = (float*)d_out;

    int n_patches = in_sizes[0] / (32 * 8 * 8);
    if (n_patches > MAX_PATCHES) n_patches = MAX_PATCHES;

    const int blocks1 = (n_patches + 7) / 8;     // 8 patches / block (1 per warp)
    reduce_kernel<<<blocks1, 256>>>(patch, n_patches);

    const int blocks2 = (n_patches + 255) / 256; // 256 patches / block (1 per thread)
    finalize_kernel<<<blocks2, 256>>>(keys, temp, beta, thr, out, n_patches);
}

// round 11
// speedup vs baseline: 1.0078x; 1.0078x over previous
#include <cuda_runtime.h>

#define FULLMASK 0xffffffffu

#define BAR_ARRIVE(id, cnt) asm volatile("bar.arrive %0, %1;" :: "r"(id), "r"(cnt) : "memory")
#define BAR_SYNC(id, cnt)   asm volatile("bar.sync %0, %1;"   :: "r"(id), "r"(cnt) : "memory")

// Block = 288 threads: warps 0-7 = producers (stream-reduce patches to smem),
// warp 8 = consumer (thread-per-patch router math). Double-buffered batches of
// 32 patches; named barriers FULL[buf]=1+buf, EMPTY[buf]=3+buf, count 288.
// Each block handles 128 patches in 4 rounds.
__global__ void __launch_bounds__(288, 2) router_kernel(
    const float* __restrict__ patch,
    const float* __restrict__ keys,
    const float* __restrict__ p_temp,
    const float* __restrict__ p_beta,
    const float* __restrict__ p_thr,
    float* __restrict__ out,
    int n_patches)
{
    __shared__ float s_keys[16][32];      // broadcast reads by consumer
    __shared__ float s_buf[2][32][33];    // [buf][patch-in-batch][channel], pad 33

    const int tid  = threadIdx.x;
    const int wid  = tid >> 5;
    const int lane = tid & 31;

    for (int i = tid; i < 16 * 32; i += 288)
        s_keys[i >> 5][i & 31] = keys[i];
    __syncthreads();

    const int block_base = blockIdx.x * 128;
    const int NT = 288;

    if (wid < 8) {
        // ======================= PRODUCERS =======================
        for (int r = 0; r < 4; r++) {
            const int buf = r & 1;
            if (r >= 2) BAR_SYNC(3 + buf, NT);        // wait consumer freed buf

#pragma unroll 1
            for (int i = 0; i < 4; i++) {
                const int lp = wid * 4 + i;           // local patch 0..31
                const int n  = block_base + r * 32 + lp;
                if (n < n_patches) {
                    const float4* p4 = reinterpret_cast<const float4*>(patch) + (size_t)n * 512;
                    float4 v[16];
#pragma unroll
                    for (int t = 0; t < 16; t++) {
                        const int p = t >> 2, q = t & 3;
                        v[t] = p4[p * 128 + (lane >> 2) * 16 + (lane & 3) + 4 * q];
                    }
#pragma unroll
                    for (int p = 0; p < 4; p++) {
                        float a = 0.0f;
#pragma unroll
                        for (int q = 0; q < 4; q++) {
                            const float4 x = v[p * 4 + q];
                            a += (x.x + x.y) + (x.z + x.w);
                        }
                        a += __shfl_xor_sync(FULLMASK, a, 1);
                        a += __shfl_xor_sync(FULLMASK, a, 2);
                        if ((lane & 3) == 0)
                            s_buf[buf][lp][p * 8 + (lane >> 2)] = a;  // raw sum
                    }
                }
            }
            BAR_ARRIVE(1 + buf, NT);                  // signal buf full
        }
    } else {
        // ======================= CONSUMER =======================
        const float logit_temp = __ldg(p_temp);
        const float mask_beta  = __ldg(p_beta);
        const float thr_base   = __ldg(p_thr);

        for (int r = 0; r < 4; r++) {
            const int buf = r & 1;
            BAR_SYNC(1 + buf, NT);                    // wait buf full

            const int n = block_base + r * 32 + lane;
            if (n < n_patches) {
                // ---- Load channel sums from smem (conflict-free: stride 33) ----
                float emb[32];
#pragma unroll
                for (int c = 0; c < 32; c++) emb[c] = s_buf[buf][lane][c];

                // ---- L2 norm ----
                float sq = 0.0f;
#pragma unroll
                for (int c = 0; c < 32; c++) sq = fmaf(emb[c], emb[c], sq);
                const float denom = fmaxf(sqrtf(sq), 64.0f * 1e-12f);

                // ---- Logits + softmax over 16 experts ----
                float w[16];
                float m = -1e30f;
#pragma unroll
                for (int e = 0; e < 16; e++) {
                    float dot = 0.0f;
#pragma unroll
                    for (int c = 0; c < 32; c++)
                        dot = fmaf(emb[c], s_keys[e][c], dot);
                    w[e] = (dot / denom) / logit_temp + 1e-8f;
                    m = fmaxf(m, w[e]);
                }
                float S = 0.0f;
#pragma unroll
                for (int e = 0; e < 16; e++) { w[e] = __expf(w[e] - m); S += w[e]; }
                const float invS = 1.0f / S;
#pragma unroll
                for (int e = 0; e < 16; e++) w[e] *= invS;

                // ---- Top-5 values (selection; values only) ----
                float t[16];
#pragma unroll
                for (int e = 0; e < 16; e++) t[e] = w[e];
                float top[5];
#pragma unroll
                for (int k = 0; k < 5; k++) {
                    float best = t[0]; int bi = 0;
#pragma unroll
                    for (int e = 1; e < 16; e++)
                        if (t[e] > best) { best = t[e]; bi = e; }
                    top[k] = best;
                    t[bi] = -1.0f;
                }
                const float s0   = top[0];
                const float rest = (top[1] + top[2] + top[3] + top[4]) * 0.25f;
                const float kth  = top[3];

                // ---- Moments & entropy ----
                float sum = 0.0f, ent = 0.0f;
#pragma unroll
                for (int e = 0; e < 16; e++) {
                    sum += w[e];
                    ent -= w[e] * __logf(w[e] + 1e-18f);
                }
                const float meanw = sum * (1.0f / 16.0f);
                float var = 0.0f;
#pragma unroll
                for (int e = 0; e < 16; e++) {
                    const float d = w[e] - meanw;
                    var = fmaf(d, d, var);
                }
                const float stdw = sqrtf(var * (1.0f / 15.0f));

                // ---- Adaptive threshold ----
                const float maxc = 1.0f - s0;
                const float entc = 1.0f - ent * (1.0f / 2.7725887222397811f);
                float gap = (s0 - rest) / (s0 + 1e-8f);
                gap = fminf(fmaxf(gap, 0.0f), 1.0f);
                const float af = 0.4f * maxc + 0.3f * entc + 0.3f * gap;
                float adaptive = thr_base * (0.5f + af);
                const float min_thr = fmaxf(0.05f, meanw - 0.5f * stdw);
                const float max_thr = fminf(0.7f, s0 - 0.1f * stdw);
                adaptive = fminf(fmaxf(adaptive, min_thr), max_thr);
                adaptive = fminf(adaptive, kth * 0.9f);

                // ---- Soft mask + renormalize ----
                float wf[16];
                float swf = 0.0f;
#pragma unroll
                for (int e = 0; e < 16; e++) {
                    const float x  = (mask_beta + 1e-8f) * (w[e] - adaptive);
                    const float sm = 1.0f / (1.0f + __expf(-x));
                    wf[e] = w[e] * sm;
                    swf += wf[e];
                }
                const float inv = 1.0f / fmaxf(swf, 1e-8f);

                float4* o4 = reinterpret_cast<float4*>(out + (size_t)n * 16);
#pragma unroll
                for (int i = 0; i < 4; i++) {
                    float4 rr;
                    rr.x = wf[i * 4 + 0] * inv; rr.y = wf[i * 4 + 1] * inv;
                    rr.z = wf[i * 4 + 2] * inv; rr.w = wf[i * 4 + 3] * inv;
                    o4[i] = rr;
                }
            }
            BAR_ARRIVE(3 + buf, NT);                  // signal buf free
        }
    }
}

extern "C" void kernel_launch(void* const* d_in, const int* in_sizes, int n_in,
                              void* d_out, int out_size) {
    const float* patch = (const float*)d_in[0];
    const float* keys  = (const float*)d_in[1];
    const float* temp  = (const float*)d_in[2];
    const float* beta  = (const float*)d_in[3];
    const float* thr   = (const float*)d_in[4];
    float* out = (float*)d_out;

    const int n_patches = in_sizes[0] / (32 * 8 * 8);
    const int blocks = (n_patches + 127) / 128;   // 128 patches per block
    router_kernel<<<blocks, 288>>>(patch, keys, temp, beta, thr, out, n_patches);
}